// round 16
// baseline (speedup 1.0000x reference)
#include <cuda_runtime.h>
#include <cuda_fp16.h>
#include <cstdint>
#include <math.h>

#define CC 256          // channels
#define GG_MAX 4096     // graphs
#define N_MAX 500000    // nodes

__device__ __align__(16) __half g_Wth[CC * CC];   // W1a^T fp16: [n][k]
__device__ float        g_sumb[GG_MAX * CC];
__device__ float        g_attb[GG_MAX * CC];
__device__ unsigned int g_maxu[GG_MAX * CC];
__device__ int          g_cnt[GG_MAX];
__device__ float        g_comb[GG_MAX * 3 * CC];
__device__ float        g_hidden[GG_MAX * CC];
__device__ int          g_is64;

// ---------------------------------------------------------------------------
// helpers
// ---------------------------------------------------------------------------
__device__ __forceinline__ uint32_t smem_u32(const void* p) {
    uint32_t a;
    asm("{ .reg .u64 t; cvta.to.shared.u64 t, %1; cvt.u32.u64 %0, t; }" : "=r"(a) : "l"(p));
    return a;
}

#define LDMX4(r0, r1, r2, r3, addr) \
    asm volatile("ldmatrix.sync.aligned.m8n8.x4.shared.b16 {%0,%1,%2,%3}, [%4];" \
        : "=r"(r0), "=r"(r1), "=r"(r2), "=r"(r3) : "r"(addr))

__device__ __forceinline__ void mma_f16(float* c, const uint32_t* a, uint32_t b0, uint32_t b1) {
    asm volatile(
        "mma.sync.aligned.m16n8k16.row.col.f32.f16.f16.f32 "
        "{%0,%1,%2,%3}, {%4,%5,%6,%7}, {%8,%9}, {%0,%1,%2,%3};"
        : "+f"(c[0]), "+f"(c[1]), "+f"(c[2]), "+f"(c[3])
        : "r"(a[0]), "r"(a[1]), "r"(a[2]), "r"(a[3]), "r"(b0), "r"(b1));
}

__device__ __forceinline__ uint32_t f2tf32(float f) {
    uint32_t r;
    asm("cvt.rna.tf32.f32 %0, %1;" : "=r"(r) : "f"(f));
    return r;
}

__device__ __forceinline__ void mma_tf32(float* c,
                                         uint32_t a0, uint32_t a1, uint32_t a2, uint32_t a3,
                                         uint32_t b0, uint32_t b1) {
    asm volatile(
        "mma.sync.aligned.m16n8k8.row.col.f32.tf32.tf32.f32 "
        "{%0,%1,%2,%3}, {%4,%5,%6,%7}, {%8,%9}, {%0,%1,%2,%3};\n"
        : "+f"(c[0]), "+f"(c[1]), "+f"(c[2]), "+f"(c[3])
        : "r"(a0), "r"(a1), "r"(a2), "r"(a3), "r"(b0), "r"(b1));
}

#define CP_COMMIT() asm volatile("cp.async.commit_group;" ::: "memory")
#define CP_WAIT1()  asm volatile("cp.async.wait_group 1;" ::: "memory")
#define CP_WAIT2()  asm volatile("cp.async.wait_group 2;" ::: "memory")

// monotone float<->uint for max on signed floats
__device__ __forceinline__ unsigned int fkey(float f) {
    unsigned int u = __float_as_uint(f);
    return (u & 0x80000000u) ? ~u : (u | 0x80000000u);
}
__device__ __forceinline__ float finv(unsigned int k) {
    unsigned int u = (k & 0x80000000u) ? (k ^ 0x80000000u) : ~k;
    return __uint_as_float(u);
}
#define KEY_NEG_INF 0x007FFFFFu   // fkey(-inf)

// ---------------------------------------------------------------------------
// batch dtype detection (int32 vs int64 view; sorted-ness discriminates)
// ---------------------------------------------------------------------------
__global__ void k0_detect(const int* __restrict__ b32, int N) {
    int i = blockIdx.x * blockDim.x + threadIdx.x;
    if (i < N - 1) {
        int a = b32[i], b = b32[i + 1];
        if (a > b || a < 0 || b < 0) g_is64 = 1;
    }
}
__device__ __forceinline__ int bseg(const void* b, int i, int is64) {
    return is64 ? (int)((const long long*)b)[i] : ((const int*)b)[i];
}

// ---------------------------------------------------------------------------
// W1a -> transposed fp16 (+ g_is64 reset; runs before k0_detect)
// ---------------------------------------------------------------------------
__global__ void k_wt(const float* __restrict__ W1a) {
    int n = blockIdx.x, k = threadIdx.x;
    if (n == 0 && k == 0) g_is64 = 0;
    g_Wth[n * CC + k] = __float2half(W1a[k * CC + n]);
}

// pooling accumulator init
__global__ void k_init() {
    int i = blockIdx.x * blockDim.x + threadIdx.x;
    g_sumb[i] = 0.f; g_attb[i] = 0.f; g_maxu[i] = KEY_NEG_INF;
    if (i < GG_MAX) g_cnt[i] = 0;
}

// ---------------------------------------------------------------------------
// K1 (fused): attention MLP (fp16 mma, B frags in regs) + segment pooling.
// CONTIGUOUS tile ranges per CTA -> per-channel segment accumulators live in
// registers across tiles; interior segments flush with PLAIN stores (owned
// exclusively); only the <=2 boundary segments per CTA use atomics.
// Seg ids ride the cp.async ring with x (resident, zero exposed latency).
// Pipeline identical to the measured 210us k1 otherwise.
// ---------------------------------------------------------------------------
#define TILE_M    32
#define RING_OFF  0            // 4 x 32768 (B fill region during prologue)
#define STG_BYTES 32768
#define A16_OFF   131072       // 2 x 16384
#define A16_BYTES 16384
#define SB1_OFF   163840
#define SW2_OFF   164864
#define PBUF_OFF  165888       // 8*32 floats
#define SAW_OFF   166912       // 32 floats
#define SSEG_OFF  167040       // 4 x 256B seg-id ring
#define K1_SMEM   168064

__device__ __forceinline__ void k1_load_stage(uint32_t sb, const float* __restrict__ x,
                                              const void* __restrict__ batch,
                                              int m0, int N, int s, int is64) {
    const int tid = threadIdx.x;
    #pragma unroll
    for (int u = 0; u < 8; ++u) {
        int idx = tid + u * 256;            // 2048 16B-chunks: 32 rows x 64 f4
        int row = idx >> 6, c4 = idx & 63;
        int node = m0 + row;
        const float* src = x + (size_t)(node < N ? node : 0) * CC + c4 * 4;
        uint32_t dst = sb + RING_OFF + s * STG_BYTES + row * 1024 + c4 * 16;
        uint32_t sz = (node < N) ? 16u : 0u;
        asm volatile("cp.async.cg.shared.global [%0], [%1], 16, %2;"
                     :: "r"(dst), "l"(src), "r"(sz));
    }
    // seg ids for this tile (32 entries; 128B int32 or 256B int64)
    const int esz = is64 ? 8 : 4;
    const int nch = (32 * esz) >> 4;        // 8 or 16 chunks
    if (tid < nch) {
        const char* srcb = (const char*)batch + (size_t)m0 * esz + tid * 16;
        uint32_t dstb = sb + SSEG_OFF + s * 256 + tid * 16;
        uint32_t szb = ((size_t)m0 * esz + (size_t)(tid + 1) * 16 <= (size_t)N * esz) ? 16u : 0u;
        asm volatile("cp.async.cg.shared.global [%0], [%1], 16, %2;"
                     :: "r"(dstb), "l"(srcb), "r"(szb));
    }
}

// convert one slice (256 of 1024 fp16-16B-chunks) of A32 stage -> A16 buf
__device__ __forceinline__ void k1_conv_slice(char* sm, int srcStage, int dstBuf, int sc) {
    const int tid = threadIdx.x;
    int idx = sc * 256 + tid;
    int row = idx >> 5, c = idx & 31;
    const float4* src = (const float4*)(sm + RING_OFF + srcStage * STG_BYTES + row * 1024 + c * 32);
    float4 v0 = src[0], v1 = src[1];
    __half2 h0 = __floats2half2_rn(v0.x, v0.y), h1 = __floats2half2_rn(v0.z, v0.w);
    __half2 h2 = __floats2half2_rn(v1.x, v1.y), h3 = __floats2half2_rn(v1.z, v1.w);
    uint4 u;
    u.x = *(uint32_t*)&h0; u.y = *(uint32_t*)&h1;
    u.z = *(uint32_t*)&h2; u.w = *(uint32_t*)&h3;
    *(uint4*)(sm + A16_OFF + dstBuf * A16_BYTES + row * 512 + ((c ^ (row & 7)) << 4)) = u;
}

// flush one segment's per-channel partials (thread = channel)
__device__ __forceinline__ void k1_flush(int seg, bool excl, float s, float a,
                                         float m, int c, int tid) {
    size_t o = (size_t)seg * CC + tid;
    if (excl) {
        g_sumb[o] = s; g_attb[o] = a; g_maxu[o] = fkey(m);
        if (tid == 0) g_cnt[seg] = c;
    } else {
        atomicAdd(&g_sumb[o], s);
        atomicAdd(&g_attb[o], a);
        atomicMax(&g_maxu[o], fkey(m));
        if (tid == 0) atomicAdd(&g_cnt[seg], c);
    }
}

__global__ void __launch_bounds__(256, 1) k1_fused(
    const float* __restrict__ x, const void* __restrict__ batch,
    const float* __restrict__ b1a, const float* __restrict__ W2a,
    const float* __restrict__ b2a, int N, int nTiles, int tilesPerCta)
{
    extern __shared__ char sm[];
    const uint32_t sb = smem_u32(sm);
    float* sB1  = (float*)(sm + SB1_OFF);
    float* sW2  = (float*)(sm + SW2_OFF);
    float* pbuf = (float*)(sm + PBUF_OFF);
    float* saw  = (float*)(sm + SAW_OFF);

    const int tid  = threadIdx.x;
    const int lane = tid & 31;
    const int w    = tid >> 5;
    const int ncol0 = w * 32;
    const int is64 = g_is64;
    const int safeTop = is64 ? (N & ~1) : (N & ~3);   // seg ids resident below this

    const int t0 = blockIdx.x * tilesPerCta;
    const int t1 = (t0 + tilesPerCta < nTiles) ? (t0 + tilesPerCta) : nTiles;

    sB1[tid] = b1a[tid];
    sW2[tid] = W2a[tid];
    const float b2 = b2a[0];

    // --- prologue: fill B smem (swizzled) in ring region, B frags -> regs ---
    #pragma unroll 4
    for (int it = 0; it < 32; ++it) {
        int idx = tid + it * 256;          // 8192 16B-chunks (256 rows x 512B)
        int row = idx >> 5, c = idx & 31;
        uint4 v = *(const uint4*)(g_Wth + (size_t)row * CC + c * 8);
        *(uint4*)(sm + RING_OFF + row * 512 + ((c ^ (row & 7)) << 4)) = v;
    }
    __syncthreads();

    const int lrow   = lane & 15;
    const int lchunk = lane >> 4;
    const int qr = lane >> 2, qc = lane & 3;

    uint32_t breg[16][2][4];
    #pragma unroll
    for (int ks = 0; ks < 16; ++ks) {
        const int kc = ks * 2 + lchunk;
        #pragma unroll
        for (int bq = 0; bq < 2; ++bq) {
            int nr = ncol0 + bq * 16 + lrow;
            uint32_t ad = sb + RING_OFF + nr * 512 + ((kc ^ (nr & 7)) << 4);
            LDMX4(breg[ks][bq][0], breg[ks][bq][1], breg[ks][bq][2], breg[ks][bq][3], ad);
        }
    }
    __syncthreads();   // B region free -> becomes A ring

    // --- prime 3 ring stages (uniform commits) ---
    #pragma unroll
    for (int j = 0; j < 3; ++j) {
        int tj = t0 + j;
        if (tj < t1) k1_load_stage(sb, x, batch, tj * TILE_M, N, j, is64);
        CP_COMMIT();
    }

    // pre-loop: convert tile t0 -> A16[0]
    if (t0 < t1) {
        CP_WAIT2();
        __syncthreads();
        #pragma unroll
        for (int sc = 0; sc < 4; ++sc) k1_conv_slice(sm, 0, 0, sc);
    }

    // pooling state (per thread = per channel), persists across tiles
    float csum = 0.f, catt = 0.f, cmx = -INFINITY;
    int   ccnt = 0, curseg = -1;
    bool  startedInside = false;

    int i = 0;
    for (int t = t0; t < t1; ++t, ++i) {
        const int b  = i & 1;
        const int s  = i & 3;
        const int m0 = t * TILE_M;
        const bool hasNext = (t + 1) < t1;

        CP_WAIT1();               // stages for tiles t and t+1 resident
        __syncthreads();          // + A16[b] visible; pbuf/saw free

        // prefetch tile t+3 (uniform commit)
        {
            int tn = t + 3;
            if (tn < t1) k1_load_stage(sb, x, batch, tn * TILE_M, N, (i + 3) & 3, is64);
            CP_COMMIT();
        }

        // mma (m32 x n32/warp x k256, B from regs) with inline convert of t+1
        float acc[2][4][4];
        #pragma unroll
        for (int mt = 0; mt < 2; ++mt)
            #pragma unroll
            for (int j = 0; j < 4; ++j) {
                acc[mt][j][0] = 0.f; acc[mt][j][1] = 0.f;
                acc[mt][j][2] = 0.f; acc[mt][j][3] = 0.f;
            }
        #pragma unroll
        for (int ks = 0; ks < 16; ++ks) {
            if ((ks & 3) == 0 && hasNext)
                k1_conv_slice(sm, (i + 1) & 3, b ^ 1, ks >> 2);
            const int kc = ks * 2 + lchunk;
            uint32_t a[2][4];
            #pragma unroll
            for (int mt = 0; mt < 2; ++mt) {
                int row = mt * 16 + lrow;
                uint32_t ad = sb + A16_OFF + b * A16_BYTES + row * 512 + ((kc ^ (row & 7)) << 4);
                LDMX4(a[mt][0], a[mt][1], a[mt][2], a[mt][3], ad);
            }
            #pragma unroll
            for (int mt = 0; mt < 2; ++mt)
                #pragma unroll
                for (int bq = 0; bq < 2; ++bq) {
                    mma_f16(acc[mt][2 * bq],     a[mt], breg[ks][bq][0], breg[ks][bq][2]);
                    mma_f16(acc[mt][2 * bq + 1], a[mt], breg[ks][bq][1], breg[ks][bq][3]);
                }
        }

        // epilogue: relu -> dot W2a (warp's n32 slice)
        float p[4] = {0.f, 0.f, 0.f, 0.f};
        #pragma unroll
        for (int mt = 0; mt < 2; ++mt)
            #pragma unroll
            for (int j = 0; j < 4; ++j) {
                int col = ncol0 + j * 8 + qc * 2;
                float bA = sB1[col], bB = sB1[col + 1];
                float wA = sW2[col], wB = sW2[col + 1];
                p[mt * 2]     += fmaxf(acc[mt][j][0] + bA, 0.f) * wA
                               + fmaxf(acc[mt][j][1] + bB, 0.f) * wB;
                p[mt * 2 + 1] += fmaxf(acc[mt][j][2] + bA, 0.f) * wA
                               + fmaxf(acc[mt][j][3] + bB, 0.f) * wB;
            }
        #pragma unroll
        for (int j = 0; j < 4; ++j) {
            p[j] += __shfl_xor_sync(0xffffffffu, p[j], 1);
            p[j] += __shfl_xor_sync(0xffffffffu, p[j], 2);
        }
        if (qc == 0) {
            pbuf[w * 32 + qr]      = p[0];
            pbuf[w * 32 + qr + 8]  = p[1];
            pbuf[w * 32 + qr + 16] = p[2];
            pbuf[w * 32 + qr + 24] = p[3];
        }
        __syncthreads();
        if (tid < 32) {
            float ssum = 0.f;
            #pragma unroll
            for (int k = 0; k < 8; ++k) ssum += pbuf[k * 32 + tid];
            saw[tid] = 1.f / (1.f + expf(-(ssum + b2)));
        }
        __syncthreads();          // saw ready; seg ids (stage s) resident

        // --- pooling from resident A32 stage; thread = channel tid ---
        {
            const int rows = (N - m0 < TILE_M) ? (N - m0) : TILE_M;
            const char* segbuf = sm + SSEG_OFF + s * 256;
            const char* xstage = sm + RING_OFF + s * STG_BYTES;
            for (int row = 0; row < rows; ++row) {
                int node = m0 + row;
                int seg = (node < safeTop)
                        ? (is64 ? (int)((const long long*)segbuf)[row]
                                : ((const int*)segbuf)[row])
                        : bseg(batch, node, is64);
                if (seg != curseg) {
                    if (curseg >= 0)
                        k1_flush(curseg, startedInside, csum, catt, cmx, ccnt, tid);
                    startedInside = (curseg >= 0);
                    curseg = seg;
                    csum = 0.f; catt = 0.f; cmx = -INFINITY; ccnt = 0;
                }
                float v  = *(const float*)(xstage + row * 1024 + tid * 4);
                float av = saw[row];
                csum += v;
                catt = fmaf(v, av, catt);
                cmx = fmaxf(cmx, v);
                ++ccnt;
            }
        }
    }
    // final segment may continue into the next CTA -> atomic
    if (curseg >= 0)
        k1_flush(curseg, false, csum, catt, cmx, ccnt, tid);
}

// fixup: combined = [att | mean | max]  (empty segments -> 0)
__global__ void k_fix() {
    int g = blockIdx.x, c = threadIdx.x;
    int cnt = g_cnt[g];
    size_t o = (size_t)g * CC + c;
    float* comb = g_comb + (size_t)g * (3 * CC);
    comb[c]          = g_attb[o];
    comb[CC + c]     = g_sumb[o] / fmaxf((float)cnt, 1.f);
    comb[2 * CC + c] = (cnt > 0) ? finv(g_maxu[o]) : 0.f;
}

// ---------------------------------------------------------------------------
// K3: tf32 mma GEMM with bias (+optional relu).
// CTA 128(M) x 64(N), 8 warps each own an m16 slab across all 64 cols.
// ---------------------------------------------------------------------------
template <bool RELU>
__global__ void __launch_bounds__(256) k3t(
    const float* __restrict__ A, const float* __restrict__ B,
    const float* __restrict__ bias, float* __restrict__ Out,
    int M, int K, int Nn)
{
    __shared__ uint32_t sA[128 * 33];
    __shared__ uint32_t sB[32 * 68];
    const int tid  = threadIdx.x;
    const int lane = tid & 31, w = tid >> 5;
    const int qr = lane >> 2, qc = lane & 3;
    const int m0 = blockIdx.y * 128, n0 = blockIdx.x * 64;
    const int row_lo = w * 16 + qr;

    float acc[8][4] = {};

    for (int kt = 0; kt < K; kt += 32) {
        __syncthreads();
        #pragma unroll
        for (int u = 0; u < 4; ++u) {
            int idx = tid + u * 256;
            int row = idx >> 3, c4 = idx & 7;
            float4 v = *(const float4*)(A + (size_t)(m0 + row) * K + kt + c4 * 4);
            uint32_t* d = sA + row * 33 + c4 * 4;
            d[0] = f2tf32(v.x); d[1] = f2tf32(v.y);
            d[2] = f2tf32(v.z); d[3] = f2tf32(v.w);
        }
        #pragma unroll
        for (int u = 0; u < 2; ++u) {
            int idx = tid + u * 256;
            int k = idx >> 4, n4 = idx & 15;
            float4 v = *(const float4*)(B + (size_t)(kt + k) * Nn + n0 + n4 * 4);
            uint32_t* d = sB + k * 68 + n4 * 4;
            d[0] = f2tf32(v.x); d[1] = f2tf32(v.y);
            d[2] = f2tf32(v.z); d[3] = f2tf32(v.w);
        }
        __syncthreads();
        #pragma unroll
        for (int kc = 0; kc < 4; ++kc) {
            int k0 = kc * 8;
            uint32_t a0 = sA[row_lo * 33 + k0 + qc];
            uint32_t a1 = sA[(row_lo + 8) * 33 + k0 + qc];
            uint32_t a2 = sA[row_lo * 33 + k0 + qc + 4];
            uint32_t a3 = sA[(row_lo + 8) * 33 + k0 + qc + 4];
            #pragma unroll
            for (int nc = 0; nc < 8; ++nc) {
                uint32_t b0 = sB[(k0 + qc) * 68 + nc * 8 + qr];
                uint32_t b1 = sB[(k0 + qc + 4) * 68 + nc * 8 + qr];
                mma_tf32(acc[nc], a0, a1, a2, a3, b0, b1);
            }
        }
    }

    #pragma unroll
    for (int nc = 0; nc < 8; ++nc) {
        int col = n0 + nc * 8 + qc * 2;
        float bA = bias[col], bB = bias[col + 1];
        float v00 = acc[nc][0] + bA, v01 = acc[nc][1] + bB;
        float v10 = acc[nc][2] + bA, v11 = acc[nc][3] + bB;
        if (RELU) {
            v00 = fmaxf(v00, 0.f); v01 = fmaxf(v01, 0.f);
            v10 = fmaxf(v10, 0.f); v11 = fmaxf(v11, 0.f);
        }
        int r0 = m0 + row_lo, r1 = r0 + 8;
        Out[(size_t)r0 * Nn + col]     = v00;
        Out[(size_t)r0 * Nn + col + 1] = v01;
        Out[(size_t)r1 * Nn + col]     = v10;
        Out[(size_t)r1 * Nn + col + 1] = v11;
    }
}

// ---------------------------------------------------------------------------
// launch
// ---------------------------------------------------------------------------
extern "C" void kernel_launch(void* const* d_in, const int* in_sizes, int n_in,
                              void* d_out, int out_size)
{
    const float* x     = (const float*)d_in[0];
    const void*  batch = d_in[1];
    const float* W1a   = (const float*)d_in[2];
    const float* b1a   = (const float*)d_in[3];
    const float* W2a   = (const float*)d_in[4];
    const float* b2a   = (const float*)d_in[5];
    const float* W1f   = (const float*)d_in[6];
    const float* b1f   = (const float*)d_in[7];
    const float* W2f   = (const float*)d_in[8];
    const float* b2f   = (const float*)d_in[9];
    float* out = (float*)d_out;

    const int N = in_sizes[0] / CC;
    const int G = out_size / CC;

    float *comb_ptr = nullptr, *hid_ptr = nullptr;
    cudaGetSymbolAddress((void**)&comb_ptr, g_comb);
    cudaGetSymbolAddress((void**)&hid_ptr, g_hidden);

    cudaFuncSetAttribute(k1_fused, cudaFuncAttributeMaxDynamicSharedMemorySize, K1_SMEM);

    k_wt<<<CC, CC>>>(W1a);                                // also resets g_is64
    k0_detect<<<(N + 255) / 256, 256>>>((const int*)batch, N);
    k_init<<<GG_MAX, 256>>>();

    const int nTiles = (N + TILE_M - 1) / TILE_M;
    const int grid = nTiles < 148 ? nTiles : 148;
    const int tilesPerCta = (nTiles + grid - 1) / grid;
    k1_fused<<<grid, 256, K1_SMEM>>>(x, batch, b1a, W2a, b2a, N, nTiles, tilesPerCta);
    k_fix<<<G, 256>>>();
    k3t<true ><<<dim3(CC / 64, G / 128), 256>>>(comb_ptr, W1f, b1f, hid_ptr, G, 3 * CC, CC);
    k3t<false><<<dim3(CC / 64, G / 128), 256>>>(hid_ptr,  W2f, b2f, out,     G, CC,     CC);
}

// round 17
// speedup vs baseline: 1.2119x; 1.2119x over previous
#include <cuda_runtime.h>
#include <cuda_fp16.h>
#include <cstdint>
#include <math.h>

#define CC 256          // channels
#define GG_MAX 4096     // graphs
#define N_MAX 500000    // nodes

__device__ float g_aw[N_MAX + 256];
__device__ __align__(16) __half g_Wth[CC * CC];   // W1a^T fp16: [n][k]
__device__ float g_comb[GG_MAX * 3 * CC];
__device__ float g_hidden[GG_MAX * CC];
__device__ int   g_is64;

// ---------------------------------------------------------------------------
// helpers
// ---------------------------------------------------------------------------
__device__ __forceinline__ uint32_t smem_u32(const void* p) {
    uint32_t a;
    asm("{ .reg .u64 t; cvta.to.shared.u64 t, %1; cvt.u32.u64 %0, t; }" : "=r"(a) : "l"(p));
    return a;
}

#define LDMX4(r0, r1, r2, r3, addr) \
    asm volatile("ldmatrix.sync.aligned.m8n8.x4.shared.b16 {%0,%1,%2,%3}, [%4];" \
        : "=r"(r0), "=r"(r1), "=r"(r2), "=r"(r3) : "r"(addr))

__device__ __forceinline__ void mma_f16(float* c, const uint32_t* a, uint32_t b0, uint32_t b1) {
    asm volatile(
        "mma.sync.aligned.m16n8k16.row.col.f32.f16.f16.f32 "
        "{%0,%1,%2,%3}, {%4,%5,%6,%7}, {%8,%9}, {%0,%1,%2,%3};"
        : "+f"(c[0]), "+f"(c[1]), "+f"(c[2]), "+f"(c[3])
        : "r"(a[0]), "r"(a[1]), "r"(a[2]), "r"(a[3]), "r"(b0), "r"(b1));
}

__device__ __forceinline__ uint32_t f2tf32(float f) {
    uint32_t r;
    asm("cvt.rna.tf32.f32 %0, %1;" : "=r"(r) : "f"(f));
    return r;
}

__device__ __forceinline__ void mma_tf32(float* c,
                                         uint32_t a0, uint32_t a1, uint32_t a2, uint32_t a3,
                                         uint32_t b0, uint32_t b1) {
    asm volatile(
        "mma.sync.aligned.m16n8k8.row.col.f32.tf32.tf32.f32 "
        "{%0,%1,%2,%3}, {%4,%5,%6,%7}, {%8,%9}, {%0,%1,%2,%3};\n"
        : "+f"(c[0]), "+f"(c[1]), "+f"(c[2]), "+f"(c[3])
        : "r"(a0), "r"(a1), "r"(a2), "r"(a3), "r"(b0), "r"(b1));
}

#define CP_COMMIT() asm volatile("cp.async.commit_group;" ::: "memory")
#define CP_WAIT1()  asm volatile("cp.async.wait_group 1;" ::: "memory")
#define CP_WAIT2()  asm volatile("cp.async.wait_group 2;" ::: "memory")

// ---------------------------------------------------------------------------
// batch dtype detection (int32 vs int64 view; sorted-ness discriminates)
// ---------------------------------------------------------------------------
__global__ void k0_detect(const int* __restrict__ b32, int N) {
    int i = blockIdx.x * blockDim.x + threadIdx.x;
    if (i < N - 1) {
        int a = b32[i], b = b32[i + 1];
        if (a > b || a < 0 || b < 0) g_is64 = 1;
    }
}
__device__ __forceinline__ long long bval(const void* b, int i) {
    if (g_is64) return ((const long long*)b)[i];
    return (long long)((const int*)b)[i];
}

// ---------------------------------------------------------------------------
// W1a -> transposed fp16 (+ g_is64 reset; runs before k0_detect)
// ---------------------------------------------------------------------------
__global__ void k_wt(const float* __restrict__ W1a) {
    int n = blockIdx.x, k = threadIdx.x;
    if (n == 0 && k == 0) g_is64 = 0;
    g_Wth[n * CC + k] = __float2half(W1a[k * CC + n]);
}

// ---------------------------------------------------------------------------
// K1 (measured ~210us): fused attention MLP, fp16 mma.sync, persistent CTAs.
// B frags in registers (warp n32 slice). 4-stage A32 ring overlaid with
// prologue-only B smem. A16 double-buffered; convert of tile t+1 interleaved
// into the mma loop of tile t.
// ---------------------------------------------------------------------------
#define TILE_M    32
#define RING_OFF  0            // 4 x 32768 (B fill region during prologue)
#define STG_BYTES 32768
#define A16_OFF   131072       // 2 x 16384
#define A16_BYTES 16384
#define SB1_OFF   163840
#define SW2_OFF   164864
#define PBUF_OFF  165888       // 8*32 floats
#define K1_SMEM   166912

__device__ __forceinline__ void k1_load_stage(uint32_t sb, const float* __restrict__ x,
                                              int m0, int N, int s) {
    const int tid = threadIdx.x;
    #pragma unroll
    for (int u = 0; u < 8; ++u) {
        int idx = tid + u * 256;            // 2048 16B-chunks: 32 rows x 64 f4
        int row = idx >> 6, c4 = idx & 63;
        int node = m0 + row;
        const float* src = x + (size_t)(node < N ? node : 0) * CC + c4 * 4;
        uint32_t dst = sb + RING_OFF + s * STG_BYTES + row * 1024 + c4 * 16;
        uint32_t sz = (node < N) ? 16u : 0u;
        asm volatile("cp.async.cg.shared.global [%0], [%1], 16, %2;"
                     :: "r"(dst), "l"(src), "r"(sz));
    }
}

// convert one slice (256 of 1024 fp16-16B-chunks) of A32 stage -> A16 buf
__device__ __forceinline__ void k1_conv_slice(char* sm, int srcStage, int dstBuf, int sc) {
    const int tid = threadIdx.x;
    int idx = sc * 256 + tid;
    int row = idx >> 5, c = idx & 31;
    const float4* src = (const float4*)(sm + RING_OFF + srcStage * STG_BYTES + row * 1024 + c * 32);
    float4 v0 = src[0], v1 = src[1];
    __half2 h0 = __floats2half2_rn(v0.x, v0.y), h1 = __floats2half2_rn(v0.z, v0.w);
    __half2 h2 = __floats2half2_rn(v1.x, v1.y), h3 = __floats2half2_rn(v1.z, v1.w);
    uint4 u;
    u.x = *(uint32_t*)&h0; u.y = *(uint32_t*)&h1;
    u.z = *(uint32_t*)&h2; u.w = *(uint32_t*)&h3;
    *(uint4*)(sm + A16_OFF + dstBuf * A16_BYTES + row * 512 + ((c ^ (row & 7)) << 4)) = u;
}

__global__ void __launch_bounds__(256, 1) k1_fp16(
    const float* __restrict__ x, const float* __restrict__ b1a,
    const float* __restrict__ W2a, const float* __restrict__ b2a,
    int N, int nTiles)
{
    extern __shared__ char sm[];
    const uint32_t sb = smem_u32(sm);
    float* sB1  = (float*)(sm + SB1_OFF);
    float* sW2  = (float*)(sm + SW2_OFF);
    float* pbuf = (float*)(sm + PBUF_OFF);

    const int tid  = threadIdx.x;
    const int lane = tid & 31;
    const int w    = tid >> 5;
    const int ncol0 = w * 32;

    sB1[tid] = b1a[tid];
    sW2[tid] = W2a[tid];
    const float b2 = b2a[0];

    // --- prologue: fill B smem (swizzled) in ring region, B frags -> regs ---
    #pragma unroll 4
    for (int it = 0; it < 32; ++it) {
        int idx = tid + it * 256;          // 8192 16B-chunks (256 rows x 512B)
        int row = idx >> 5, c = idx & 31;
        uint4 v = *(const uint4*)(g_Wth + (size_t)row * CC + c * 8);
        *(uint4*)(sm + RING_OFF + row * 512 + ((c ^ (row & 7)) << 4)) = v;
    }
    __syncthreads();

    const int lrow   = lane & 15;
    const int lchunk = lane >> 4;
    const int qr = lane >> 2, qc = lane & 3;

    uint32_t breg[16][2][4];
    #pragma unroll
    for (int ks = 0; ks < 16; ++ks) {
        const int kc = ks * 2 + lchunk;
        #pragma unroll
        for (int bq = 0; bq < 2; ++bq) {
            int nr = ncol0 + bq * 16 + lrow;
            uint32_t ad = sb + RING_OFF + nr * 512 + ((kc ^ (nr & 7)) << 4);
            LDMX4(breg[ks][bq][0], breg[ks][bq][1], breg[ks][bq][2], breg[ks][bq][3], ad);
        }
    }
    __syncthreads();   // B region free -> becomes A ring

    // --- prime 3 ring stages (uniform commits) ---
    #pragma unroll
    for (int j = 0; j < 3; ++j) {
        int tj = blockIdx.x + j * gridDim.x;
        if (tj < nTiles) k1_load_stage(sb, x, tj * TILE_M, N, j);
        CP_COMMIT();
    }

    // pre-loop: convert tile0 -> A16[0]
    if (blockIdx.x < nTiles) {
        CP_WAIT2();               // stage 0 resident
        __syncthreads();
        #pragma unroll
        for (int sc = 0; sc < 4; ++sc) k1_conv_slice(sm, 0, 0, sc);
    }

    int i = 0;
    for (int t = blockIdx.x; t < nTiles; t += gridDim.x, ++i) {
        const int b  = i & 1;
        const int m0 = t * TILE_M;
        const bool hasNext = (t + gridDim.x) < nTiles;

        CP_WAIT1();               // stage (i+1)&3 (tile t+1) resident
        __syncthreads();          // + A16[b] visible; pbuf free

        // prefetch tile t+3 into stage (i+3)&3; uniform commit
        {
            int tn = t + 3 * gridDim.x;
            if (tn < nTiles) k1_load_stage(sb, x, tn * TILE_M, N, (i + 3) & 3);
            CP_COMMIT();
        }

        // mma (m32 x n32/warp x k256, B from regs) with inline convert of t+1
        float acc[2][4][4];
        #pragma unroll
        for (int mt = 0; mt < 2; ++mt)
            #pragma unroll
            for (int j = 0; j < 4; ++j) {
                acc[mt][j][0] = 0.f; acc[mt][j][1] = 0.f;
                acc[mt][j][2] = 0.f; acc[mt][j][3] = 0.f;
            }
        #pragma unroll
        for (int ks = 0; ks < 16; ++ks) {
            if ((ks & 3) == 0 && hasNext)
                k1_conv_slice(sm, (i + 1) & 3, b ^ 1, ks >> 2);
            const int kc = ks * 2 + lchunk;
            uint32_t a[2][4];
            #pragma unroll
            for (int mt = 0; mt < 2; ++mt) {
                int row = mt * 16 + lrow;
                uint32_t ad = sb + A16_OFF + b * A16_BYTES + row * 512 + ((kc ^ (row & 7)) << 4);
                LDMX4(a[mt][0], a[mt][1], a[mt][2], a[mt][3], ad);
            }
            #pragma unroll
            for (int mt = 0; mt < 2; ++mt)
                #pragma unroll
                for (int bq = 0; bq < 2; ++bq) {
                    mma_f16(acc[mt][2 * bq],     a[mt], breg[ks][bq][0], breg[ks][bq][2]);
                    mma_f16(acc[mt][2 * bq + 1], a[mt], breg[ks][bq][1], breg[ks][bq][3]);
                }
        }

        // epilogue: relu -> dot W2a (warp's n32 slice)
        float p[4] = {0.f, 0.f, 0.f, 0.f};   // rows qr, qr+8, 16+qr, 24+qr
        #pragma unroll
        for (int mt = 0; mt < 2; ++mt)
            #pragma unroll
            for (int j = 0; j < 4; ++j) {
                int col = ncol0 + j * 8 + qc * 2;
                float bA = sB1[col], bB = sB1[col + 1];
                float wA = sW2[col], wB = sW2[col + 1];
                p[mt * 2]     += fmaxf(acc[mt][j][0] + bA, 0.f) * wA
                               + fmaxf(acc[mt][j][1] + bB, 0.f) * wB;
                p[mt * 2 + 1] += fmaxf(acc[mt][j][2] + bA, 0.f) * wA
                               + fmaxf(acc[mt][j][3] + bB, 0.f) * wB;
            }
        #pragma unroll
        for (int j = 0; j < 4; ++j) {
            p[j] += __shfl_xor_sync(0xffffffffu, p[j], 1);
            p[j] += __shfl_xor_sync(0xffffffffu, p[j], 2);
        }
        if (qc == 0) {
            pbuf[w * 32 + qr]      = p[0];
            pbuf[w * 32 + qr + 8]  = p[1];
            pbuf[w * 32 + qr + 16] = p[2];
            pbuf[w * 32 + qr + 24] = p[3];
        }
        __syncthreads();
        if (tid < 32) {
            float ssum = 0.f;
            #pragma unroll
            for (int k = 0; k < 8; ++k) ssum += pbuf[k * 32 + tid];
            int node = m0 + tid;
            if (node < N) g_aw[node] = 1.f / (1.f + expf(-(ssum + b2)));
        }
    }
}

// ---------------------------------------------------------------------------
// K2 (round-2 original, measured 130.7us): one CTA per graph, thread c owns
// channel c, scalar loads. regs=32 -> full 8-CTA residency (RF exactly full).
// No atomics, deterministic.
// ---------------------------------------------------------------------------
__global__ void __launch_bounds__(256) k2_pool(
    const float* __restrict__ x, const void* __restrict__ batch, int N)
{
    const int g = blockIdx.x;
    __shared__ int sR[2];
    if (threadIdx.x == 0) {
        int lo = 0, hi = N;
        while (lo < hi) { int mid = (lo + hi) >> 1; if (bval(batch, mid) < (long long)g) lo = mid + 1; else hi = mid; }
        sR[0] = lo;
        hi = N;
        while (lo < hi) { int mid = (lo + hi) >> 1; if (bval(batch, mid) < (long long)g + 1) lo = mid + 1; else hi = mid; }
        sR[1] = lo;
    }
    __syncthreads();
    const int s = sR[0], e = sR[1];
    const int c = threadIdx.x;

    float sum = 0.f, att = 0.f, mx = -INFINITY;
    for (int i = s; i < e; ++i) {
        float v = x[(size_t)i * CC + c];
        float w = g_aw[i];
        sum += v;
        att = fmaf(v, w, att);
        mx = fmaxf(mx, v);
    }
    float cnt  = (float)(e - s);
    float mean = sum / fmaxf(cnt, 1.f);
    float mxo  = (e > s) ? mx : 0.f;   // empty segments -> 0

    float* comb = g_comb + (size_t)g * (3 * CC);
    comb[c]          = att;
    comb[CC + c]     = mean;
    comb[2 * CC + c] = mxo;
}

// ---------------------------------------------------------------------------
// K3: tf32 mma GEMM with bias (+optional relu).
// CTA 128(M) x 64(N), 8 warps each own an m16 slab across all 64 cols.
// ---------------------------------------------------------------------------
template <bool RELU>
__global__ void __launch_bounds__(256) k3t(
    const float* __restrict__ A, const float* __restrict__ B,
    const float* __restrict__ bias, float* __restrict__ Out,
    int M, int K, int Nn)
{
    __shared__ uint32_t sA[128 * 33];   // [row][k], k-stride 33
    __shared__ uint32_t sB[32 * 68];    // [k][n], n-stride 68
    const int tid  = threadIdx.x;
    const int lane = tid & 31, w = tid >> 5;
    const int qr = lane >> 2, qc = lane & 3;
    const int m0 = blockIdx.y * 128, n0 = blockIdx.x * 64;
    const int row_lo = w * 16 + qr;

    float acc[8][4] = {};

    for (int kt = 0; kt < K; kt += 32) {
        __syncthreads();
        #pragma unroll
        for (int u = 0; u < 4; ++u) {
            int idx = tid + u * 256;        // 1024 f4
            int row = idx >> 3, c4 = idx & 7;
            float4 v = *(const float4*)(A + (size_t)(m0 + row) * K + kt + c4 * 4);
            uint32_t* d = sA + row * 33 + c4 * 4;
            d[0] = f2tf32(v.x); d[1] = f2tf32(v.y);
            d[2] = f2tf32(v.z); d[3] = f2tf32(v.w);
        }
        #pragma unroll
        for (int u = 0; u < 2; ++u) {
            int idx = tid + u * 256;        // 512 f4
            int k = idx >> 4, n4 = idx & 15;
            float4 v = *(const float4*)(B + (size_t)(kt + k) * Nn + n0 + n4 * 4);
            uint32_t* d = sB + k * 68 + n4 * 4;
            d[0] = f2tf32(v.x); d[1] = f2tf32(v.y);
            d[2] = f2tf32(v.z); d[3] = f2tf32(v.w);
        }
        __syncthreads();
        #pragma unroll
        for (int kc = 0; kc < 4; ++kc) {
            int k0 = kc * 8;
            uint32_t a0 = sA[row_lo * 33 + k0 + qc];
            uint32_t a1 = sA[(row_lo + 8) * 33 + k0 + qc];
            uint32_t a2 = sA[row_lo * 33 + k0 + qc + 4];
            uint32_t a3 = sA[(row_lo + 8) * 33 + k0 + qc + 4];
            #pragma unroll
            for (int nc = 0; nc < 8; ++nc) {
                uint32_t b0 = sB[(k0 + qc) * 68 + nc * 8 + qr];
                uint32_t b1 = sB[(k0 + qc + 4) * 68 + nc * 8 + qr];
                mma_tf32(acc[nc], a0, a1, a2, a3, b0, b1);
            }
        }
    }

    #pragma unroll
    for (int nc = 0; nc < 8; ++nc) {
        int col = n0 + nc * 8 + qc * 2;
        float bA = bias[col], bB = bias[col + 1];
        float v00 = acc[nc][0] + bA, v01 = acc[nc][1] + bB;
        float v10 = acc[nc][2] + bA, v11 = acc[nc][3] + bB;
        if (RELU) {
            v00 = fmaxf(v00, 0.f); v01 = fmaxf(v01, 0.f);
            v10 = fmaxf(v10, 0.f); v11 = fmaxf(v11, 0.f);
        }
        int r0 = m0 + row_lo, r1 = r0 + 8;
        Out[(size_t)r0 * Nn + col]     = v00;
        Out[(size_t)r0 * Nn + col + 1] = v01;
        Out[(size_t)r1 * Nn + col]     = v10;
        Out[(size_t)r1 * Nn + col + 1] = v11;
    }
}

// ---------------------------------------------------------------------------
// launch
// ---------------------------------------------------------------------------
extern "C" void kernel_launch(void* const* d_in, const int* in_sizes, int n_in,
                              void* d_out, int out_size)
{
    const float* x     = (const float*)d_in[0];
    const void*  batch = d_in[1];
    const float* W1a   = (const float*)d_in[2];
    const float* b1a   = (const float*)d_in[3];
    const float* W2a   = (const float*)d_in[4];
    const float* b2a   = (const float*)d_in[5];
    const float* W1f   = (const float*)d_in[6];
    const float* b1f   = (const float*)d_in[7];
    const float* W2f   = (const float*)d_in[8];
    const float* b2f   = (const float*)d_in[9];
    float* out = (float*)d_out;

    const int N = in_sizes[0] / CC;
    const int G = out_size / CC;

    float *comb_ptr = nullptr, *hid_ptr = nullptr;
    cudaGetSymbolAddress((void**)&comb_ptr, g_comb);
    cudaGetSymbolAddress((void**)&hid_ptr, g_hidden);

    cudaFuncSetAttribute(k1_fp16, cudaFuncAttributeMaxDynamicSharedMemorySize, K1_SMEM);

    k_wt<<<CC, CC>>>(W1a);                                // also resets g_is64
    k0_detect<<<(N + 255) / 256, 256>>>((const int*)batch, N);

    const int nTiles = (N + TILE_M - 1) / TILE_M;
    const int grid = nTiles < 148 ? nTiles : 148;
    k1_fp16<<<grid, 256, K1_SMEM>>>(x, b1a, W2a, b2a, N, nTiles);
    k2_pool<<<G, 256>>>(x, batch, N);
    k3t<true ><<<dim3(CC / 64, G / 128), 256>>>(comb_ptr, W1f, b1f, hid_ptr, G, 3 * CC, CC);
    k3t<false><<<dim3(CC / 64, G / 128), 256>>>(hid_ptr,  W2f, b2f, out,     G, CC,     CC);
}